// round 15
// baseline (speedup 1.0000x reference)
#include <cuda_runtime.h>
#include <math.h>
#include <stdint.h>

#define HIDDEN  256
#define N_PROT  12288
#define N_MOL   6144
#define N_BATCH 32
#define TQ      16                      // prot rows per attn block
#define MSEG    384                     // max mol rows per batch (mean 192, sd 13.6 -> 14 sigma)
#define CKEYS   16                      // K rows per chunk (x2 buffers = 32 KB)
#define CKBYTES (CKEYS * HIDDEN * 4)    // 16 KB per buffer
#define MAXTILES (N_PROT / TQ + N_BATCH)

// proj tiling: 128x64 tile, BK=16, 8x4 microtile, 256 threads, occ 4
#define PBM 128
#define PBN 64
#define PBK 16
#define XSTRIDE 136                     // PBM + 8
#define WSTRIDE 72                      // PBN + 8
#define NPROJ 768                       // Q: 96*4=384, K: 48*4=192, V: 192

// Scratch (device globals: allocation-free per harness rules)
__device__ float g_Q[N_PROT * HIDDEN];
__device__ float g_K[N_MOL * HIDDEN];
__device__ float g_V[N_MOL * HIDDEN];
__device__ int   g_ms[N_BATCH + 1];
__device__ int   g_ps[N_BATCH + 1];
__device__ int   g_ss[N_BATCH];
__device__ int   g_se[N_BATCH];
__device__ int   g_trow[MAXTILES];
__device__ int   g_tn[MAXTILES];
__device__ int   g_tb[MAXTILES];
__device__ int   g_ntiles;

// ---- f32x2 helpers (FFMA2 is PTX-only; ptxas never auto-fuses) -----------
__device__ __forceinline__ unsigned long long ffma2(
    unsigned long long a, unsigned long long b, unsigned long long c)
{
    unsigned long long d;
    asm("fma.rn.f32x2 %0, %1, %2, %3;" : "=l"(d) : "l"(a), "l"(b), "l"(c));
    return d;
}
__device__ __forceinline__ unsigned long long pack2(float lo, float hi)
{
    unsigned long long p;
    asm("mov.b64 %0, {%1, %2};" : "=l"(p) : "f"(lo), "f"(hi));
    return p;
}
__device__ __forceinline__ void unpack2(unsigned long long p, float& lo, float& hi)
{
    asm("mov.b64 {%0, %1}, %2;" : "=f"(lo), "=f"(hi) : "l"(p));
}
// 128-bit shared load as two pre-paired f32x2 operands (ONE LDS.128)
__device__ __forceinline__ void lds_v2u64(
    unsigned long long& a, unsigned long long& b, uint32_t addr)
{
    asm volatile("ld.shared.v2.u64 {%0, %1}, [%2];" : "=l"(a), "=l"(b) : "r"(addr));
}
// cp.async 16B global->shared (LDGSTS; no result registers)
__device__ __forceinline__ void cp_async16(uint32_t saddr, const void* gaddr)
{
    asm volatile("cp.async.cg.shared.global [%0], [%1], 16;"
                 :: "r"(saddr), "l"(gaddr));
}
#define CP_COMMIT() asm volatile("cp.async.commit_group;")
#define CP_WAIT0()  asm volatile("cp.async.wait_group 0;" ::: "memory")

// ---------------------------------------------------------------------------
// Parallel boundary detection on the SORTED batch arrays.
// ---------------------------------------------------------------------------
__global__ __launch_bounds__(256) void bounds_kernel(
    const int* __restrict__ prot_batch, const int* __restrict__ mol_batch)
{
    const int i = blockIdx.x * 256 + threadIdx.x;
    if (i < N_MOL) {
        const int v = mol_batch[i];
        const int p = (i > 0) ? mol_batch[i - 1] : -1;
        for (int bb = p + 1; bb <= v; bb++) g_ms[bb] = i;
        if (i == N_MOL - 1)
            for (int bb = v + 1; bb <= N_BATCH; bb++) g_ms[bb] = N_MOL;
    }
    if (i < N_PROT) {
        const int v = prot_batch[i];
        const int p = (i > 0) ? prot_batch[i - 1] : -1;
        for (int bb = p + 1; bb <= v; bb++) g_ps[bb] = i;
        if (i == N_PROT - 1)
            for (int bb = v + 1; bb <= N_BATCH; bb++) g_ps[bb] = N_PROT;
    }
}

// ---------------------------------------------------------------------------
// Tile build: 1 warp.
// ---------------------------------------------------------------------------
__global__ void tiles_kernel()
{
    const int tid = threadIdx.x;
    if (tid >= 32) return;
    g_ss[tid] = g_ms[tid];
    g_se[tid] = g_ms[tid + 1];

    const int p0 = g_ps[tid];
    const int np = g_ps[tid + 1] - p0;
    const int nt = (np + TQ - 1) / TQ;
    int off = nt;
    #pragma unroll
    for (int d = 1; d < 32; d <<= 1) {
        const int n = __shfl_up_sync(0xffffffffu, off, d);
        if (tid >= d) off += n;
    }
    const int base = off - nt;
    for (int k = 0; k < nt; k++) {
        g_trow[base + k] = p0 + k * TQ;
        g_tn[base + k]   = (np - k * TQ < TQ) ? (np - k * TQ) : TQ;
        g_tb[base + k]   = tid;
    }
    if (tid == 31) g_ntiles = off;
}

// ---------------------------------------------------------------------------
// Fused projection GEMMs, 128x64 tile / BK=16 / 8x4 microtile, f32x2.
// Smaller acc (32 regs) -> ~63 regs -> occ 4 -> grid 768 balances across SMs
// (4% wave quantization vs the 30% tail of the 384-block 128x128 version).
// ---------------------------------------------------------------------------
__global__ __launch_bounds__(256, 4) void proj_kernel(
    const float* __restrict__ prot_embed, const float* __restrict__ mol_embed,
    const float* __restrict__ Wq, const float* __restrict__ bq,
    const float* __restrict__ Wk, const float* __restrict__ bk,
    const float* __restrict__ Wv, const float* __restrict__ bv)
{
    __shared__ __align__(16) float XsT[PBK * XSTRIDE];   // [k][row], 8.7 KB
    __shared__ __align__(16) float WsT[PBK * WSTRIDE];   // [k][col], 4.6 KB

    const int gb = blockIdx.x;
    const float* X; const float* W; const float* bias; float* C;
    int local;
    if (gb < 384)      { local = gb;       X = prot_embed; W = Wq; bias = bq; C = g_Q; }
    else if (gb < 576) { local = gb - 384; X = mol_embed;  W = Wk; bias = bk; C = g_K; }
    else               { local = gb - 576; X = mol_embed;  W = Wv; bias = bv; C = g_V; }
    const int row0 = (local >> 2) * PBM;
    const int col0 = (local & 3) * PBN;

    const int tid = threadIdx.x;
    const int tx  = tid & 15;            // 0..15 -> 4 cols each (64 cols)
    const int ty  = tid >> 4;            // 0..15 -> 4+4 rows each (128 rows)

    const uint32_t xst_base = (uint32_t)__cvta_generic_to_shared(XsT);

    // acc2[rp][c]: rp0=(ty*4+0,1) rp1=(ty*4+2,3) rp2=(64+ty*4+0,1) rp3=(64+ty*4+2,3)
    unsigned long long acc2[4][4] = {};

    for (int k0 = 0; k0 < HIDDEN; k0 += PBK) {
        // Stage X (128 rows x 16 k): 512 float4, 2 per thread.
        #pragma unroll
        for (int u = 0; u < 2; u++) {
            const int idx = u * 256 + tid;
            const int r   = idx >> 2;
            const int c4  = idx & 3;
            const float4 xv = *(const float4*)(X + (size_t)(row0 + r) * HIDDEN + k0 + c4 * 4);
            XsT[(c4 * 4 + 0) * XSTRIDE + r] = xv.x;
            XsT[(c4 * 4 + 1) * XSTRIDE + r] = xv.y;
            XsT[(c4 * 4 + 2) * XSTRIDE + r] = xv.z;
            XsT[(c4 * 4 + 3) * XSTRIDE + r] = xv.w;
        }
        // Stage W (64 rows x 16 k): 256 float4, 1 per thread.
        {
            const int r  = tid >> 2;
            const int c4 = tid & 3;
            const float4 wv = *(const float4*)(W + (size_t)(col0 + r) * HIDDEN + k0 + c4 * 4);
            WsT[(c4 * 4 + 0) * WSTRIDE + r] = wv.x;
            WsT[(c4 * 4 + 1) * WSTRIDE + r] = wv.y;
            WsT[(c4 * 4 + 2) * WSTRIDE + r] = wv.z;
            WsT[(c4 * 4 + 3) * WSTRIDE + r] = wv.w;
        }
        __syncthreads();

        #pragma unroll
        for (int kk = 0; kk < PBK; kk++) {
            const uint32_t xrow = xst_base + (uint32_t)(kk * XSTRIDE) * 4u;
            // A: 8 rows as 4 pre-paired f32x2 (broadcast within half-warp)
            unsigned long long a01, a23, a45, a67;
            lds_v2u64(a01, a23, xrow + (uint32_t)(ty * 4) * 4u);
            lds_v2u64(a45, a67, xrow + (uint32_t)(64 + ty * 4) * 4u);
            // B: 4 cols via one LDS.128, splat-packed
            const float4 bv4 = *(const float4*)&WsT[kk * WSTRIDE + tx * 4];
            const unsigned long long bb[4] = {
                pack2(bv4.x, bv4.x), pack2(bv4.y, bv4.y),
                pack2(bv4.z, bv4.z), pack2(bv4.w, bv4.w)
            };
            #pragma unroll
            for (int c = 0; c < 4; c++) {
                acc2[0][c] = ffma2(a01, bb[c], acc2[0][c]);
                acc2[1][c] = ffma2(a23, bb[c], acc2[1][c]);
                acc2[2][c] = ffma2(a45, bb[c], acc2[2][c]);
                acc2[3][c] = ffma2(a67, bb[c], acc2[3][c]);
            }
        }
        __syncthreads();
    }

    // Epilogue: unpack, add bias, store 8 rows x 4 cols per thread.
    const float4 bl = *(const float4*)(bias + col0 + tx * 4);
    #pragma unroll
    for (int rp = 0; rp < 4; rp++) {
        const int r0 = (rp < 2) ? (ty * 4 + rp * 2) : (64 + ty * 4 + (rp - 2) * 2);
        float lo[4], hi[4];
        #pragma unroll
        for (int c = 0; c < 4; c++) unpack2(acc2[rp][c], lo[c], hi[c]);
        float* R0 = C + (size_t)(row0 + r0) * HIDDEN;
        float* R1 = C + (size_t)(row0 + r0 + 1) * HIDDEN;
        *(float4*)(R0 + col0 + tx * 4) = make_float4(lo[0]+bl.x, lo[1]+bl.y, lo[2]+bl.z, lo[3]+bl.w);
        *(float4*)(R1 + col0 + tx * 4) = make_float4(hi[0]+bl.x, hi[1]+bl.y, hi[2]+bl.z, hi[3]+bl.w);
    }
}

// ---------------------------------------------------------------------------
// Attention (R14 core; K staging now cp.async DOUBLE-BUFFERED so chunk c+1
// streams in while chunk c is computed — removes the staged-load exposure).
// ---------------------------------------------------------------------------
__global__ __launch_bounds__(256, 3) void attn_kernel(
    float* __restrict__ out, float* __restrict__ attn)
{
    const int t = blockIdx.x;
    if (t >= g_ntiles) return;

    const int row0 = g_trow[t];
    const int nr   = g_tn[t];
    const int b    = g_tb[t];
    const int s    = g_ss[b];
    int m = g_se[b] - s;
    if (m > MSEG) m = MSEG;          // unreachable; memory safety
    const int e_eff = s + m;

    __shared__ __align__(16) float sc[TQ * MSEG];          // 24 KB, [row][key]
    __shared__ __align__(16) float Ks[2 * CKEYS * HIDDEN]; // 2 x 16 KB

    const int tid  = threadIdx.x;
    const int warp = tid >> 5;
    const int lane = tid & 31;

    const uint32_t ks_base = (uint32_t)__cvta_generic_to_shared(Ks);
    const uint32_t sc_base = (uint32_t)__cvta_generic_to_shared(sc);

    if (m > 0) {
        const int g  = warp & 3;
        const int kh = warp >> 2;
        const int h  = lane >> 4;
        const int hl = lane & 15;
        const int rA = g * 4 + h * 2;
        const int rB = rA + 1;
        const int qrA = row0 + ((rA < nr) ? rA : nr - 1);
        const int qrB = row0 + ((rB < nr) ? rB : nr - 1);

        unsigned long long qpA[8], qpB[8];
        {
            const float4* QA = (const float4*)g_Q + (size_t)qrA * 64;
            const float4* QB = (const float4*)g_Q + (size_t)qrB * 64;
            #pragma unroll
            for (int i = 0; i < 4; i++) {
                const float4 fa = QA[hl + 16 * i];
                const float4 fb = QB[hl + 16 * i];
                qpA[2 * i]     = pack2(fa.x, fa.y);
                qpA[2 * i + 1] = pack2(fa.z, fa.w);
                qpB[2 * i]     = pack2(fb.x, fb.y);
                qpB[2 * i + 1] = pack2(fb.z, fb.w);
            }
        }

        const int nchunks = (m + CKEYS - 1) / CKEYS;

        // Preload chunk 0 into buffer 0 (cp.async, 16B each).
        {
            const float4* Kg = (const float4*)g_K + (size_t)s * 64;
            const int lim = ((m < CKEYS) ? m : CKEYS) * 64;
            for (int idx = tid; idx < lim; idx += 256)
                cp_async16(ks_base + (uint32_t)idx * 16u, Kg + idx);
            CP_COMMIT();
        }
        CP_WAIT0();
        __syncthreads();

        for (int ci = 0; ci < nchunks; ci++) {
            const int c0 = ci * CKEYS;
            const int cn = (m - c0 < CKEYS) ? (m - c0) : CKEYS;
            const uint32_t cur_base = ks_base + (uint32_t)(ci & 1) * CKBYTES;

            // Kick off the next chunk into the other buffer.
            if (c0 + CKEYS < m) {
                const int n0 = c0 + CKEYS;
                const int nn = ((m - n0 < CKEYS) ? (m - n0) : CKEYS) * 64;
                const float4* Kg = (const float4*)g_K + (size_t)(s + n0) * 64;
                const uint32_t nb = ks_base + (uint32_t)((ci + 1) & 1) * CKBYTES;
                for (int idx = tid; idx < nn; idx += 256)
                    cp_async16(nb + (uint32_t)idx * 16u, Kg + idx);
                CP_COMMIT();
            }

            const int jlo = kh ? (cn >> 1) : 0;
            const int jhi = kh ? cn : (cn >> 1);
            #pragma unroll 2
            for (int j = jlo; j < jhi; j++) {
                const uint32_t kb = cur_base + (uint32_t)j * 1024u + (uint32_t)hl * 16u;
                unsigned long long k0, k1, k2, k3, k4, k5, k6, k7;
                lds_v2u64(k0, k1, kb);
                lds_v2u64(k2, k3, kb + 256u);
                lds_v2u64(k4, k5, kb + 512u);
                lds_v2u64(k6, k7, kb + 768u);
                unsigned long long a0 = ffma2(qpA[0], k0, 0ull);
                unsigned long long a1 = ffma2(qpA[1], k1, 0ull);
                unsigned long long b0 = ffma2(qpB[0], k0, 0ull);
                unsigned long long b1 = ffma2(qpB[1], k1, 0ull);
                a0 = ffma2(qpA[2], k2, a0);  b0 = ffma2(qpB[2], k2, b0);
                a1 = ffma2(qpA[3], k3, a1);  b1 = ffma2(qpB[3], k3, b1);
                a0 = ffma2(qpA[4], k4, a0);  b0 = ffma2(qpB[4], k4, b0);
                a1 = ffma2(qpA[5], k5, a1);  b1 = ffma2(qpB[5], k5, b1);
                a0 = ffma2(qpA[6], k6, a0);  b0 = ffma2(qpB[6], k6, b0);
                a1 = ffma2(qpA[7], k7, a1);  b1 = ffma2(qpB[7], k7, b1);
                float al, ah, bl, bh, cl, ch, dl, dh;
                unpack2(a0, al, ah);
                unpack2(a1, bl, bh);
                unpack2(b0, cl, ch);
                unpack2(b1, dl, dh);
                float dA = (al + ah) + (bl + bh);
                float dB = (cl + ch) + (dl + dh);
                #pragma unroll
                for (int off = 8; off; off >>= 1) {
                    dA += __shfl_xor_sync(0xffffffffu, dA, off);
                    dB += __shfl_xor_sync(0xffffffffu, dB, off);
                }
                if (hl == 0) {
                    sc[rA * MSEG + c0 + j] = dA * 0.0625f;   // 1/sqrt(256)
                    sc[rB * MSEG + c0 + j] = dB * 0.0625f;
                }
            }

            CP_WAIT0();        // next buffer landed (no-op on last chunk)
            __syncthreads();   // also protects buffer reuse next iteration
        }

        // Softmax: warp w normalizes rows 2w, 2w+1.
        #pragma unroll
        for (int rr2 = 0; rr2 < 2; rr2++) {
            float* row = sc + (warp * 2 + rr2) * MSEG;
            float mx = -INFINITY;
            for (int j = lane; j < m; j += 32) mx = fmaxf(mx, row[j]);
            #pragma unroll
            for (int off = 16; off; off >>= 1)
                mx = fmaxf(mx, __shfl_xor_sync(0xffffffffu, mx, off));
            float sum = 0.f;
            for (int j = lane; j < m; j += 32) {
                const float v = __expf(row[j] - mx);
                row[j] = v;
                sum += v;
            }
            #pragma unroll
            for (int off = 16; off; off >>= 1)
                sum += __shfl_xor_sync(0xffffffffu, sum, off);
            const float inv = 1.f / sum;
            for (int j = lane; j < m; j += 32) row[j] *= inv;
        }
        __syncthreads();
    }

    // FULL attn-row write (zeros outside [s, e_eff)) — replaces the memset.
    for (int r = 0; r < nr; r++) {
        float4* arow = (float4*)(attn + (size_t)(row0 + r) * N_MOL);
        const float* row = sc + r * MSEG;
        for (int c4 = tid; c4 < N_MOL / 4; c4 += 256) {
            const int c = c4 * 4;
            float4 v = {0.f, 0.f, 0.f, 0.f};
            if (m > 0 && c + 3 >= s && c < e_eff) {
                if (c + 0 >= s && c + 0 < e_eff) v.x = row[c + 0 - s];
                if (c + 1 >= s && c + 1 < e_eff) v.y = row[c + 1 - s];
                if (c + 2 >= s && c + 2 < e_eff) v.z = row[c + 2 - s];
                if (c + 3 >= s && c + 3 < e_eff) v.w = row[c + 3 - s];
            }
            arow[c4] = v;
        }
    }

    // ---- PV: acc2[r] f32x2, lo/hi = even/odd key partials; V loads
    //      software-pipelined (R14, measured win). ----
    unsigned long long acc2[TQ];
    #pragma unroll
    for (int r = 0; r < TQ; r++) acc2[r] = 0ull;

    int j = 0;
    if (m >= 4) {
        float nv0 = g_V[(size_t)(s + 0) * HIDDEN + tid];
        float nv1 = g_V[(size_t)(s + 1) * HIDDEN + tid];
        float nv2 = g_V[(size_t)(s + 2) * HIDDEN + tid];
        float nv3 = g_V[(size_t)(s + 3) * HIDDEN + tid];
        for (; j + 3 < m; j += 4) {
            const float v0 = nv0, v1 = nv1, v2 = nv2, v3 = nv3;
            const int jn = (j + 7 < m) ? (j + 4) : j;   // clamp (re-read ok)
            nv0 = g_V[(size_t)(s + jn + 0) * HIDDEN + tid];
            nv1 = g_V[(size_t)(s + jn + 1) * HIDDEN + tid];
            nv2 = g_V[(size_t)(s + jn + 2) * HIDDEN + tid];
            nv3 = g_V[(size_t)(s + jn + 3) * HIDDEN + tid];
            const unsigned long long vv01 = pack2(v0, v1);
            const unsigned long long vv23 = pack2(v2, v3);
            #pragma unroll
            for (int r = 0; r < TQ; r++) {
                unsigned long long p01, p23;
                lds_v2u64(p01, p23, sc_base + (uint32_t)(r * MSEG + j) * 4u);
                unsigned long long a = acc2[r];
                a = ffma2(p01, vv01, a);
                a = ffma2(p23, vv23, a);
                acc2[r] = a;
            }
        }
    }
    for (; j < m; j++) {
        const float v0 = g_V[(size_t)(s + j) * HIDDEN + tid];
        const unsigned long long vv = pack2(v0, 0.f);
        #pragma unroll
        for (int r = 0; r < TQ; r++) {
            const unsigned long long pp = pack2(sc[r * MSEG + j], 0.f);
            acc2[r] = ffma2(pp, vv, acc2[r]);
        }
    }

    #pragma unroll
    for (int r = 0; r < TQ; r++) {
        float lo, hi;
        unpack2(acc2[r], lo, hi);
        if (r < nr) out[(size_t)(row0 + r) * HIDDEN + tid] = lo + hi;
    }
}

// ---------------------------------------------------------------------------
extern "C" void kernel_launch(void* const* d_in, const int* in_sizes, int n_in,
                              void* d_out, int out_size)
{
    const float* prot_embed = (const float*)d_in[0];
    const float* mol_embed  = (const float*)d_in[1];
    const int*   prot_batch = (const int*)d_in[2];
    const int*   mol_batch  = (const int*)d_in[3];
    const float* Wq = (const float*)d_in[4];
    const float* bq = (const float*)d_in[5];
    const float* Wk = (const float*)d_in[6];
    const float* bk = (const float*)d_in[7];
    const float* Wv = (const float*)d_in[8];
    const float* bv = (const float*)d_in[9];

    float* out  = (float*)d_out;                              // [N_PROT, HIDDEN]
    float* attn = (float*)d_out + (size_t)N_PROT * HIDDEN;    // [N_PROT, N_MOL]

    bounds_kernel<<<(N_PROT + 255) / 256, 256>>>(prot_batch, mol_batch);
    tiles_kernel<<<1, 32>>>();
    proj_kernel<<<NPROJ, 256>>>(prot_embed, mol_embed, Wq, bq, Wk, bk, Wv, bv);
    attn_kernel<<<MAXTILES, 256>>>(out, attn);
}

// round 16
// speedup vs baseline: 1.0544x; 1.0544x over previous
#include <cuda_runtime.h>
#include <math.h>
#include <stdint.h>

#define HIDDEN  256
#define N_PROT  12288
#define N_MOL   6144
#define N_BATCH 32
#define TQ      16                      // prot rows per attn block
#define MSEG    384                     // max mol rows per batch (mean 192, sd 13.6 -> 14 sigma)
#define CKEYS   16                      // K rows per chunk (x2 buffers = 32 KB)
#define CKBYTES (CKEYS * HIDDEN * 4)    // 16 KB per buffer
#define MAXTILES (N_PROT / TQ + N_BATCH)

// proj tiling: 128x128 tile, BK=16, 8x8 microtile, 256 threads (R11 config)
#define PBM 128
#define PBK 16
#define PSTRIDE 136                     // PBM + 8: stride%32==8 -> conflict-free scattered STS
#define NPROJ 384                       // Q: 96*2=192, K: 48*2=96, V: 96

// Scratch (device globals: allocation-free per harness rules)
__device__ float g_Q[N_PROT * HIDDEN];
__device__ float g_K[N_MOL * HIDDEN];
__device__ float g_V[N_MOL * HIDDEN];
__device__ int   g_ms[N_BATCH + 1];
__device__ int   g_ps[N_BATCH + 1];
__device__ int   g_ss[N_BATCH];
__device__ int   g_se[N_BATCH];
__device__ int   g_trow[MAXTILES];
__device__ int   g_tn[MAXTILES];
__device__ int   g_tb[MAXTILES];
__device__ int   g_ntiles;

// ---- f32x2 helpers (FFMA2 is PTX-only; ptxas never auto-fuses) -----------
__device__ __forceinline__ unsigned long long ffma2(
    unsigned long long a, unsigned long long b, unsigned long long c)
{
    unsigned long long d;
    asm("fma.rn.f32x2 %0, %1, %2, %3;" : "=l"(d) : "l"(a), "l"(b), "l"(c));
    return d;
}
__device__ __forceinline__ unsigned long long pack2(float lo, float hi)
{
    unsigned long long p;
    asm("mov.b64 %0, {%1, %2};" : "=l"(p) : "f"(lo), "f"(hi));
    return p;
}
__device__ __forceinline__ void unpack2(unsigned long long p, float& lo, float& hi)
{
    asm("mov.b64 {%0, %1}, %2;" : "=f"(lo), "=f"(hi) : "l"(p));
}
// 128-bit shared load as two pre-paired f32x2 operands (ONE LDS.128)
__device__ __forceinline__ void lds_v2u64(
    unsigned long long& a, unsigned long long& b, uint32_t addr)
{
    asm volatile("ld.shared.v2.u64 {%0, %1}, [%2];" : "=l"(a), "=l"(b) : "r"(addr));
}
// cp.async 16B global->shared (LDGSTS; no result registers)
__device__ __forceinline__ void cp_async16(uint32_t saddr, const void* gaddr)
{
    asm volatile("cp.async.cg.shared.global [%0], [%1], 16;"
                 :: "r"(saddr), "l"(gaddr));
}
#define CP_COMMIT() asm volatile("cp.async.commit_group;")
#define CP_WAIT0()  asm volatile("cp.async.wait_group 0;" ::: "memory")

// ---------------------------------------------------------------------------
// Parallel boundary detection on the SORTED batch arrays.
// ---------------------------------------------------------------------------
__global__ __launch_bounds__(256) void bounds_kernel(
    const int* __restrict__ prot_batch, const int* __restrict__ mol_batch)
{
    const int i = blockIdx.x * 256 + threadIdx.x;
    if (i < N_MOL) {
        const int v = mol_batch[i];
        const int p = (i > 0) ? mol_batch[i - 1] : -1;
        for (int bb = p + 1; bb <= v; bb++) g_ms[bb] = i;
        if (i == N_MOL - 1)
            for (int bb = v + 1; bb <= N_BATCH; bb++) g_ms[bb] = N_MOL;
    }
    if (i < N_PROT) {
        const int v = prot_batch[i];
        const int p = (i > 0) ? prot_batch[i - 1] : -1;
        for (int bb = p + 1; bb <= v; bb++) g_ps[bb] = i;
        if (i == N_PROT - 1)
            for (int bb = v + 1; bb <= N_BATCH; bb++) g_ps[bb] = N_PROT;
    }
}

// ---------------------------------------------------------------------------
// Tile build: 1 warp.
// ---------------------------------------------------------------------------
__global__ void tiles_kernel()
{
    const int tid = threadIdx.x;
    if (tid >= 32) return;
    g_ss[tid] = g_ms[tid];
    g_se[tid] = g_ms[tid + 1];

    const int p0 = g_ps[tid];
    const int np = g_ps[tid + 1] - p0;
    const int nt = (np + TQ - 1) / TQ;
    int off = nt;
    #pragma unroll
    for (int d = 1; d < 32; d <<= 1) {
        const int n = __shfl_up_sync(0xffffffffu, off, d);
        if (tid >= d) off += n;
    }
    const int base = off - nt;
    for (int k = 0; k < nt; k++) {
        g_trow[base + k] = p0 + k * TQ;
        g_tn[base + k]   = (np - k * TQ < TQ) ? (np - k * TQ) : TQ;
        g_tb[base + k]   = tid;
    }
    if (tid == 31) g_ntiles = off;
}

// ---------------------------------------------------------------------------
// Fused projection GEMMs, 128x128 tile / BK=16 / 8x8 microtile, f32x2
// (R11 config — measured best) + REGISTER PREFETCH of the next k0 panel so
// global-load latency hides behind the 16-kk FFMA2 block.
// ---------------------------------------------------------------------------
__global__ __launch_bounds__(256, 2) void proj_kernel(
    const float* __restrict__ prot_embed, const float* __restrict__ mol_embed,
    const float* __restrict__ Wq, const float* __restrict__ bq,
    const float* __restrict__ Wk, const float* __restrict__ bk,
    const float* __restrict__ Wv, const float* __restrict__ bv)
{
    __shared__ __align__(16) float XsT[PBK * PSTRIDE];   // [k][row]
    __shared__ __align__(16) float WsT[PBK * PSTRIDE];   // [k][col]

    const int gb = blockIdx.x;
    const float* X; const float* W; const float* bias; float* C;
    int local;
    if (gb < 192)      { local = gb;       X = prot_embed; W = Wq; bias = bq; C = g_Q; }
    else if (gb < 288) { local = gb - 192; X = mol_embed;  W = Wk; bias = bk; C = g_K; }
    else               { local = gb - 288; X = mol_embed;  W = Wv; bias = bv; C = g_V; }
    const int row0 = (local >> 1) * PBM;
    const int col0 = (local & 1) * PBM;

    const int tid = threadIdx.x;
    const int tx  = tid & 15;
    const int ty  = tid >> 4;

    const uint32_t xst_base = (uint32_t)__cvta_generic_to_shared(XsT);

    // Per-thread staging coordinates (2 float4 per matrix per panel).
    const int sr0 = (tid) >> 2,        sc0 = (tid) & 3;
    const int sr1 = (256 + tid) >> 2,  sc1 = (256 + tid) & 3;

    unsigned long long acc2[4][8] = {};

    // Prefetch panel k0=0 into registers.
    float4 px0 = *(const float4*)(X + (size_t)(row0 + sr0) * HIDDEN + sc0 * 4);
    float4 pw0 = *(const float4*)(W + (size_t)(col0 + sr0) * HIDDEN + sc0 * 4);
    float4 px1 = *(const float4*)(X + (size_t)(row0 + sr1) * HIDDEN + sc1 * 4);
    float4 pw1 = *(const float4*)(W + (size_t)(col0 + sr1) * HIDDEN + sc1 * 4);

    for (int k0 = 0; k0 < HIDDEN; k0 += PBK) {
        // Store the prefetched panel (transposed, conflict-free scatter).
        XsT[(sc0 * 4 + 0) * PSTRIDE + sr0] = px0.x;
        XsT[(sc0 * 4 + 1) * PSTRIDE + sr0] = px0.y;
        XsT[(sc0 * 4 + 2) * PSTRIDE + sr0] = px0.z;
        XsT[(sc0 * 4 + 3) * PSTRIDE + sr0] = px0.w;
        WsT[(sc0 * 4 + 0) * PSTRIDE + sr0] = pw0.x;
        WsT[(sc0 * 4 + 1) * PSTRIDE + sr0] = pw0.y;
        WsT[(sc0 * 4 + 2) * PSTRIDE + sr0] = pw0.z;
        WsT[(sc0 * 4 + 3) * PSTRIDE + sr0] = pw0.w;
        XsT[(sc1 * 4 + 0) * PSTRIDE + sr1] = px1.x;
        XsT[(sc1 * 4 + 1) * PSTRIDE + sr1] = px1.y;
        XsT[(sc1 * 4 + 2) * PSTRIDE + sr1] = px1.z;
        XsT[(sc1 * 4 + 3) * PSTRIDE + sr1] = px1.w;
        WsT[(sc1 * 4 + 0) * PSTRIDE + sr1] = pw1.x;
        WsT[(sc1 * 4 + 1) * PSTRIDE + sr1] = pw1.y;
        WsT[(sc1 * 4 + 2) * PSTRIDE + sr1] = pw1.z;
        WsT[(sc1 * 4 + 3) * PSTRIDE + sr1] = pw1.w;
        __syncthreads();

        // Prefetch next panel while computing this one.
        if (k0 + PBK < HIDDEN) {
            const int kn = k0 + PBK;
            px0 = *(const float4*)(X + (size_t)(row0 + sr0) * HIDDEN + kn + sc0 * 4);
            pw0 = *(const float4*)(W + (size_t)(col0 + sr0) * HIDDEN + kn + sc0 * 4);
            px1 = *(const float4*)(X + (size_t)(row0 + sr1) * HIDDEN + kn + sc1 * 4);
            pw1 = *(const float4*)(W + (size_t)(col0 + sr1) * HIDDEN + kn + sc1 * 4);
        }

        #pragma unroll
        for (int kk = 0; kk < PBK; kk++) {
            const uint32_t xrow = xst_base + (uint32_t)(kk * PSTRIDE) * 4u;
            unsigned long long a01, a23, a45, a67;
            lds_v2u64(a01, a23, xrow + (uint32_t)(ty * 4) * 4u);
            lds_v2u64(a45, a67, xrow + (uint32_t)(64 + ty * 4) * 4u);
            const float4 blo = *(const float4*)&WsT[kk * PSTRIDE + tx * 4];
            const float4 bhi = *(const float4*)&WsT[kk * PSTRIDE + 64 + tx * 4];
            const unsigned long long bb[8] = {
                pack2(blo.x, blo.x), pack2(blo.y, blo.y),
                pack2(blo.z, blo.z), pack2(blo.w, blo.w),
                pack2(bhi.x, bhi.x), pack2(bhi.y, bhi.y),
                pack2(bhi.z, bhi.z), pack2(bhi.w, bhi.w)
            };
            #pragma unroll
            for (int c = 0; c < 8; c++) {
                acc2[0][c] = ffma2(a01, bb[c], acc2[0][c]);
                acc2[1][c] = ffma2(a23, bb[c], acc2[1][c]);
                acc2[2][c] = ffma2(a45, bb[c], acc2[2][c]);
                acc2[3][c] = ffma2(a67, bb[c], acc2[3][c]);
            }
        }
        __syncthreads();
    }

    const float4 bl = *(const float4*)(bias + col0 + tx * 4);
    const float4 bh = *(const float4*)(bias + col0 + 64 + tx * 4);
    #pragma unroll
    for (int rp = 0; rp < 4; rp++) {
        const int r0 = (rp < 2) ? (ty * 4 + rp * 2) : (64 + ty * 4 + (rp - 2) * 2);
        float lo[8], hi[8];
        #pragma unroll
        for (int c = 0; c < 8; c++) unpack2(acc2[rp][c], lo[c], hi[c]);
        float* R0 = C + (size_t)(row0 + r0) * HIDDEN;
        float* R1 = C + (size_t)(row0 + r0 + 1) * HIDDEN;
        *(float4*)(R0 + col0 + tx * 4)      = make_float4(lo[0]+bl.x, lo[1]+bl.y, lo[2]+bl.z, lo[3]+bl.w);
        *(float4*)(R0 + col0 + 64 + tx * 4) = make_float4(lo[4]+bh.x, lo[5]+bh.y, lo[6]+bh.z, lo[7]+bh.w);
        *(float4*)(R1 + col0 + tx * 4)      = make_float4(hi[0]+bl.x, hi[1]+bl.y, hi[2]+bl.z, hi[3]+bl.w);
        *(float4*)(R1 + col0 + 64 + tx * 4) = make_float4(hi[4]+bh.x, hi[5]+bh.y, hi[6]+bh.z, hi[7]+bh.w);
    }
}

// ---------------------------------------------------------------------------
// Attention (R15 — measured 165.9us): cp.async double-buffered K staging,
// f32x2 score + softmax + full-row attn write + software-pipelined PV.
// ---------------------------------------------------------------------------
__global__ __launch_bounds__(256, 3) void attn_kernel(
    float* __restrict__ out, float* __restrict__ attn)
{
    const int t = blockIdx.x;
    if (t >= g_ntiles) return;

    const int row0 = g_trow[t];
    const int nr   = g_tn[t];
    const int b    = g_tb[t];
    const int s    = g_ss[b];
    int m = g_se[b] - s;
    if (m > MSEG) m = MSEG;          // unreachable; memory safety
    const int e_eff = s + m;

    __shared__ __align__(16) float sc[TQ * MSEG];          // 24 KB, [row][key]
    __shared__ __align__(16) float Ks[2 * CKEYS * HIDDEN]; // 2 x 16 KB

    const int tid  = threadIdx.x;
    const int warp = tid >> 5;
    const int lane = tid & 31;

    const uint32_t ks_base = (uint32_t)__cvta_generic_to_shared(Ks);
    const uint32_t sc_base = (uint32_t)__cvta_generic_to_shared(sc);

    if (m > 0) {
        const int g  = warp & 3;
        const int kh = warp >> 2;
        const int h  = lane >> 4;
        const int hl = lane & 15;
        const int rA = g * 4 + h * 2;
        const int rB = rA + 1;
        const int qrA = row0 + ((rA < nr) ? rA : nr - 1);
        const int qrB = row0 + ((rB < nr) ? rB : nr - 1);

        unsigned long long qpA[8], qpB[8];
        {
            const float4* QA = (const float4*)g_Q + (size_t)qrA * 64;
            const float4* QB = (const float4*)g_Q + (size_t)qrB * 64;
            #pragma unroll
            for (int i = 0; i < 4; i++) {
                const float4 fa = QA[hl + 16 * i];
                const float4 fb = QB[hl + 16 * i];
                qpA[2 * i]     = pack2(fa.x, fa.y);
                qpA[2 * i + 1] = pack2(fa.z, fa.w);
                qpB[2 * i]     = pack2(fb.x, fb.y);
                qpB[2 * i + 1] = pack2(fb.z, fb.w);
            }
        }

        const int nchunks = (m + CKEYS - 1) / CKEYS;

        // Preload chunk 0 into buffer 0 (cp.async, 16B each).
        {
            const float4* Kg = (const float4*)g_K + (size_t)s * 64;
            const int lim = ((m < CKEYS) ? m : CKEYS) * 64;
            for (int idx = tid; idx < lim; idx += 256)
                cp_async16(ks_base + (uint32_t)idx * 16u, Kg + idx);
            CP_COMMIT();
        }
        CP_WAIT0();
        __syncthreads();

        for (int ci = 0; ci < nchunks; ci++) {
            const int c0 = ci * CKEYS;
            const int cn = (m - c0 < CKEYS) ? (m - c0) : CKEYS;
            const uint32_t cur_base = ks_base + (uint32_t)(ci & 1) * CKBYTES;

            // Kick off the next chunk into the other buffer.
            if (c0 + CKEYS < m) {
                const int n0 = c0 + CKEYS;
                const int nn = ((m - n0 < CKEYS) ? (m - n0) : CKEYS) * 64;
                const float4* Kg = (const float4*)g_K + (size_t)(s + n0) * 64;
                const uint32_t nb = ks_base + (uint32_t)((ci + 1) & 1) * CKBYTES;
                for (int idx = tid; idx < nn; idx += 256)
                    cp_async16(nb + (uint32_t)idx * 16u, Kg + idx);
                CP_COMMIT();
            }

            const int jlo = kh ? (cn >> 1) : 0;
            const int jhi = kh ? cn : (cn >> 1);
            #pragma unroll 2
            for (int j = jlo; j < jhi; j++) {
                const uint32_t kb = cur_base + (uint32_t)j * 1024u + (uint32_t)hl * 16u;
                unsigned long long k0, k1, k2, k3, k4, k5, k6, k7;
                lds_v2u64(k0, k1, kb);
                lds_v2u64(k2, k3, kb + 256u);
                lds_v2u64(k4, k5, kb + 512u);
                lds_v2u64(k6, k7, kb + 768u);
                unsigned long long a0 = ffma2(qpA[0], k0, 0ull);
                unsigned long long a1 = ffma2(qpA[1], k1, 0ull);
                unsigned long long b0 = ffma2(qpB[0], k0, 0ull);
                unsigned long long b1 = ffma2(qpB[1], k1, 0ull);
                a0 = ffma2(qpA[2], k2, a0);  b0 = ffma2(qpB[2], k2, b0);
                a1 = ffma2(qpA[3], k3, a1);  b1 = ffma2(qpB[3], k3, b1);
                a0 = ffma2(qpA[4], k4, a0);  b0 = ffma2(qpB[4], k4, b0);
                a1 = ffma2(qpA[5], k5, a1);  b1 = ffma2(qpB[5], k5, b1);
                a0 = ffma2(qpA[6], k6, a0);  b0 = ffma2(qpB[6], k6, b0);
                a1 = ffma2(qpA[7], k7, a1);  b1 = ffma2(qpB[7], k7, b1);
                float al, ah, bl, bh, cl, ch, dl, dh;
                unpack2(a0, al, ah);
                unpack2(a1, bl, bh);
                unpack2(b0, cl, ch);
                unpack2(b1, dl, dh);
                float dA = (al + ah) + (bl + bh);
                float dB = (cl + ch) + (dl + dh);
                #pragma unroll
                for (int off = 8; off; off >>= 1) {
                    dA += __shfl_xor_sync(0xffffffffu, dA, off);
                    dB += __shfl_xor_sync(0xffffffffu, dB, off);
                }
                if (hl == 0) {
                    sc[rA * MSEG + c0 + j] = dA * 0.0625f;   // 1/sqrt(256)
                    sc[rB * MSEG + c0 + j] = dB * 0.0625f;
                }
            }

            CP_WAIT0();        // next buffer landed (no-op on last chunk)
            __syncthreads();   // also protects buffer reuse next iteration
        }

        // Softmax: warp w normalizes rows 2w, 2w+1.
        #pragma unroll
        for (int rr2 = 0; rr2 < 2; rr2++) {
            float* row = sc + (warp * 2 + rr2) * MSEG;
            float mx = -INFINITY;
            for (int j = lane; j < m; j += 32) mx = fmaxf(mx, row[j]);
            #pragma unroll
            for (int off = 16; off; off >>= 1)
                mx = fmaxf(mx, __shfl_xor_sync(0xffffffffu, mx, off));
            float sum = 0.f;
            for (int j = lane; j < m; j += 32) {
                const float v = __expf(row[j] - mx);
                row[j] = v;
                sum += v;
            }
            #pragma unroll
            for (int off = 16; off; off >>= 1)
                sum += __shfl_xor_sync(0xffffffffu, sum, off);
            const float inv = 1.f / sum;
            for (int j = lane; j < m; j += 32) row[j] *= inv;
        }
        __syncthreads();
    }

    // FULL attn-row write (zeros outside [s, e_eff)) — replaces the memset.
    for (int r = 0; r < nr; r++) {
        float4* arow = (float4*)(attn + (size_t)(row0 + r) * N_MOL);
        const float* row = sc + r * MSEG;
        for (int c4 = tid; c4 < N_MOL / 4; c4 += 256) {
            const int c = c4 * 4;
            float4 v = {0.f, 0.f, 0.f, 0.f};
            if (m > 0 && c + 3 >= s && c < e_eff) {
                if (c + 0 >= s && c + 0 < e_eff) v.x = row[c + 0 - s];
                if (c + 1 >= s && c + 1 < e_eff) v.y = row[c + 1 - s];
                if (c + 2 >= s && c + 2 < e_eff) v.z = row[c + 2 - s];
                if (c + 3 >= s && c + 3 < e_eff) v.w = row[c + 3 - s];
            }
            arow[c4] = v;
        }
    }

    // ---- PV: acc2[r] f32x2, lo/hi = even/odd key partials; V loads
    //      software-pipelined (R14, measured win). ----
    unsigned long long acc2[TQ];
    #pragma unroll
    for (int r = 0; r < TQ; r++) acc2[r] = 0ull;

    int j = 0;
    if (m >= 4) {
        float nv0 = g_V[(size_t)(s + 0) * HIDDEN + tid];
        float nv1 = g_V[(size_t)(s + 1) * HIDDEN + tid];
        float nv2 = g_V[(size_t)(s + 2) * HIDDEN + tid];
        float nv3 = g_V[(size_t)(s + 3) * HIDDEN + tid];
        for (; j + 3 < m; j += 4) {
            const float v0 = nv0, v1 = nv1, v2 = nv2, v3 = nv3;
            const int jn = (j + 7 < m) ? (j + 4) : j;   // clamp (re-read ok)
            nv0 = g_V[(size_t)(s + jn + 0) * HIDDEN + tid];
            nv1 = g_V[(size_t)(s + jn + 1) * HIDDEN + tid];
            nv2 = g_V[(size_t)(s + jn + 2) * HIDDEN + tid];
            nv3 = g_V[(size_t)(s + jn + 3) * HIDDEN + tid];
            const unsigned long long vv01 = pack2(v0, v1);
            const unsigned long long vv23 = pack2(v2, v3);
            #pragma unroll
            for (int r = 0; r < TQ; r++) {
                unsigned long long p01, p23;
                lds_v2u64(p01, p23, sc_base + (uint32_t)(r * MSEG + j) * 4u);
                unsigned long long a = acc2[r];
                a = ffma2(p01, vv01, a);
                a = ffma2(p23, vv23, a);
                acc2[r] = a;
            }
        }
    }
    for (; j < m; j++) {
        const float v0 = g_V[(size_t)(s + j) * HIDDEN + tid];
        const unsigned long long vv = pack2(v0, 0.f);
        #pragma unroll
        for (int r = 0; r < TQ; r++) {
            const unsigned long long pp = pack2(sc[r * MSEG + j], 0.f);
            acc2[r] = ffma2(pp, vv, acc2[r]);
        }
    }

    #pragma unroll
    for (int r = 0; r < TQ; r++) {
        float lo, hi;
        unpack2(acc2[r], lo, hi);
        if (r < nr) out[(size_t)(row0 + r) * HIDDEN + tid] = lo + hi;
    }
}

// ---------------------------------------------------------------------------
extern "C" void kernel_launch(void* const* d_in, const int* in_sizes, int n_in,
                              void* d_out, int out_size)
{
    const float* prot_embed = (const float*)d_in[0];
    const float* mol_embed  = (const float*)d_in[1];
    const int*   prot_batch = (const int*)d_in[2];
    const int*   mol_batch  = (const int*)d_in[3];
    const float* Wq = (const float*)d_in[4];
    const float* bq = (const float*)d_in[5];
    const float* Wk = (const float*)d_in[6];
    const float* bk = (const float*)d_in[7];
    const float* Wv = (const float*)d_in[8];
    const float* bv = (const float*)d_in[9];

    float* out  = (float*)d_out;                              // [N_PROT, HIDDEN]
    float* attn = (float*)d_out + (size_t)N_PROT * HIDDEN;    // [N_PROT, N_MOL]

    bounds_kernel<<<(N_PROT + 255) / 256, 256>>>(prot_batch, mol_batch);
    tiles_kernel<<<1, 32>>>();
    proj_kernel<<<NPROJ, 256>>>(prot_embed, mol_embed, Wq, bq, Wk, bk, Wv, bv);
    attn_kernel<<<MAXTILES, 256>>>(out, attn);
}